// round 7
// baseline (speedup 1.0000x reference)
#include <cuda_runtime.h>
#include <cooperative_groups.h>
#include <stdint.h>
#include <math.h>

namespace cg = cooperative_groups;

#define BATCH  256
#define NPTS   16384
#define THREADS 512
#define HALF_GROUPS (NPTS / 4 / 2)            // 2048 groups of 4 pts per CTA
#define GPT (HALF_GROUPS / THREADS)           // 4 groups per thread
#define SMEM_BYTES (HALF_GROUPS * 3 * 16)     // 98304 B staged masked pred

// ---------------------------------------------------------------------------
// FP32 3x3 Kabsch solve helpers
// ---------------------------------------------------------------------------
__device__ __forceinline__ float nrsqrt(float s) {
    float n = rsqrtf(s);
    return n * (1.5f - 0.5f * s * n * n);
}

__device__ __forceinline__ void jrotf(float S[3][3], float V[3][3], int p, int q) {
    float apq = S[p][q];
    if (fabsf(apq) < 1e-30f) return;
    float theta = (S[q][q] - S[p][p]) / (2.0f * apq);
    float t = copysignf(1.0f, theta) / (fabsf(theta) + sqrtf(theta * theta + 1.0f));
    float c = nrsqrt(t * t + 1.0f);
    float s = t * c;
    int r = 3 - p - q;
    float Spp = S[p][p], Sqq = S[q][q];
    S[p][p] = Spp - t * apq;
    S[q][q] = Sqq + t * apq;
    S[p][q] = S[q][p] = 0.0f;
    float Srp = S[r][p], Srq = S[r][q];
    S[r][p] = S[p][r] = c * Srp - s * Srq;
    S[r][q] = S[q][r] = s * Srp + c * Srq;
#pragma unroll
    for (int i = 0; i < 3; i++) {
        float vp = V[i][p], vq = V[i][q];
        V[i][p] = c * vp - s * vq;
        V[i][q] = s * vp + c * vq;
    }
}

__device__ void kabsch_solve(const float* sums, float* rt) {
    float W = sums[0];
    float invW = 1.0f / W;
    float Swp[3] = {sums[1], sums[2], sums[3]};
    float Swt[3] = {sums[4], sums[5], sums[6]};

    float A[3][3];
#pragma unroll
    for (int i = 0; i < 3; i++)
#pragma unroll
        for (int j = 0; j < 3; j++)
            A[i][j] = sums[7 + 3 * i + j] - Swt[i] * Swp[j] * invW;

    float S[3][3];
#pragma unroll
    for (int j = 0; j < 3; j++)
#pragma unroll
        for (int k = 0; k < 3; k++)
            S[j][k] = A[0][j] * A[0][k] + A[1][j] * A[1][k] + A[2][j] * A[2][k];

    float V[3][3] = {{1,0,0},{0,1,0},{0,0,1}};
#pragma unroll
    for (int sweep = 0; sweep < 12; sweep++) {
        jrotf(S, V, 0, 1);
        jrotf(S, V, 0, 2);
        jrotf(S, V, 1, 2);
    }

    float d[3] = {S[0][0], S[1][1], S[2][2]};
    int id[3] = {0, 1, 2};
    if (d[id[0]] < d[id[1]]) { int t = id[0]; id[0] = id[1]; id[1] = t; }
    if (d[id[0]] < d[id[2]]) { int t = id[0]; id[0] = id[2]; id[2] = t; }
    if (d[id[1]] < d[id[2]]) { int t = id[1]; id[1] = id[2]; id[2] = t; }

    float v1[3], v2[3], v3[3];
#pragma unroll
    for (int i = 0; i < 3; i++) { v1[i] = V[i][id[0]]; v2[i] = V[i][id[1]]; v3[i] = V[i][id[2]]; }

    float u1[3], u2[3];
#pragma unroll
    for (int i = 0; i < 3; i++) u1[i] = A[i][0]*v1[0] + A[i][1]*v1[1] + A[i][2]*v1[2];
    float n1 = nrsqrt(u1[0]*u1[0] + u1[1]*u1[1] + u1[2]*u1[2] + 1e-37f);
#pragma unroll
    for (int i = 0; i < 3; i++) u1[i] *= n1;
#pragma unroll
    for (int i = 0; i < 3; i++) u2[i] = A[i][0]*v2[0] + A[i][1]*v2[1] + A[i][2]*v2[2];
    float dp = u2[0]*u1[0] + u2[1]*u1[1] + u2[2]*u1[2];
#pragma unroll
    for (int i = 0; i < 3; i++) u2[i] -= dp * u1[i];
    float n2 = nrsqrt(u2[0]*u2[0] + u2[1]*u2[1] + u2[2]*u2[2] + 1e-37f);
#pragma unroll
    for (int i = 0; i < 3; i++) u2[i] *= n2;

    float detraw = v1[0]*(v2[1]*v3[2] - v2[2]*v3[1])
                 - v1[1]*(v2[0]*v3[2] - v2[2]*v3[0])
                 + v1[2]*(v2[0]*v3[1] - v2[1]*v3[0]);
    float detV = (detraw >= 0.0f) ? 1.0f : -1.0f;
    float u3[3] = {
        detV * (u1[1]*u2[2] - u1[2]*u2[1]),
        detV * (u1[2]*u2[0] - u1[0]*u2[2]),
        detV * (u1[0]*u2[1] - u1[1]*u2[0])
    };

#pragma unroll
    for (int i = 0; i < 3; i++)
#pragma unroll
        for (int j = 0; j < 3; j++)
            rt[3*i + j] = u1[i]*v1[j] + u2[i]*v2[j] + u3[i]*v3[j];
#pragma unroll
    for (int j = 0; j < 3; j++) rt[9  + j] = Swp[j] * invW;
#pragma unroll
    for (int i = 0; i < 3; i++) rt[12 + i] = Swt[i] * invW;
}

// ---------------------------------------------------------------------------
// Fused cluster kernel: 2 CTAs per batch. Each CTA stages half the batch's
// masked pred in 96KB SMEM and accumulates partial moments; partial sums are
// exchanged across the cluster via DSMEM; each CTA solves (redundantly) and
// applies its own half.
// ---------------------------------------------------------------------------
extern __shared__ float4 spred[];  // HALF_GROUPS*3 float4 = 96 KB

__global__ void __launch_bounds__(THREADS, 2) __cluster_dims__(2, 1, 1)
wra_fused(
    const float* __restrict__ pred,
    const float* __restrict__ truec,
    const float* __restrict__ wts,
    const uint32_t* __restrict__ mask,
    float* __restrict__ out)
{
    cg::cluster_group cluster = cg::this_cluster();
    const int rank = (int)cluster.block_rank();    // 0 or 1
    const int b = blockIdx.x >> 1;                 // batch index
    const int gofs = rank * HALF_GROUPS;           // group offset of this half

    const float4* __restrict__ p4 = reinterpret_cast<const float4*>(pred  + (size_t)b * NPTS * 3);
    const float4* __restrict__ t4 = reinterpret_cast<const float4*>(truec + (size_t)b * NPTS * 3);
    const float4* __restrict__ w4 = reinterpret_cast<const float4*>(wts   + (size_t)b * NPTS);
    const uint4* __restrict__ m4  = reinterpret_cast<const uint4*>(mask + (size_t)b * NPTS);

    float acc[16];
#pragma unroll
    for (int i = 0; i < 16; i++) acc[i] = 0.f;

    // -------- Phase 1: stream own half, accumulate, stage masked pred ------
#pragma unroll
    for (int it = 0; it < GPT; it++) {
        const int gl = it * THREADS + threadIdx.x;   // local group
        const int g  = gofs + gl;                    // global group
        float4 a0 = __ldcs(&p4[3*g+0]), a1 = __ldcs(&p4[3*g+1]), a2 = __ldcs(&p4[3*g+2]);
        float4 c0 = __ldcs(&t4[3*g+0]), c1 = __ldcs(&t4[3*g+1]), c2 = __ldcs(&t4[3*g+2]);
        float4 wv = __ldcs(&w4[g]);
        uint4  mv = __ldcs(&m4[g]);

        float px[4] = {a0.x, a0.w, a1.z, a2.y};
        float py[4] = {a0.y, a1.x, a1.w, a2.z};
        float pz[4] = {a0.z, a1.y, a2.x, a2.w};
        float tx[4] = {c0.x, c0.w, c1.z, c2.y};
        float ty[4] = {c0.y, c1.x, c1.w, c2.z};
        float tz[4] = {c0.z, c1.y, c2.x, c2.w};
        float ww[4] = {wv.x, wv.y, wv.z, wv.w};
        uint32_t mm[4] = {mv.x, mv.y, mv.z, mv.w};

        float mp[12];
#pragma unroll
        for (int k = 0; k < 4; k++) {
            bool mk = (mm[k] != 0u);
            float mx = mk ? px[k] : 0.f;
            float my = mk ? py[k] : 0.f;
            float mz = mk ? pz[k] : 0.f;
            mp[3*k+0] = mx; mp[3*k+1] = my; mp[3*k+2] = mz;

            float wi = mk ? ww[k] : 0.f;
            float wtx = wi * tx[k], wty = wi * ty[k], wtz = wi * tz[k];
            acc[0]  += wi;
            acc[1]  += wi * mx;
            acc[2]  += wi * my;
            acc[3]  += wi * mz;
            acc[4]  += wtx;
            acc[5]  += wty;
            acc[6]  += wtz;
            acc[7]  += wtx * mx;
            acc[8]  += wtx * my;
            acc[9]  += wtx * mz;
            acc[10] += wty * mx;
            acc[11] += wty * my;
            acc[12] += wty * mz;
            acc[13] += wtz * mx;
            acc[14] += wtz * my;
            acc[15] += wtz * mz;
        }
        spred[3*gl+0] = make_float4(mp[0],  mp[1],  mp[2],  mp[3]);
        spred[3*gl+1] = make_float4(mp[4],  mp[5],  mp[6],  mp[7]);
        spred[3*gl+2] = make_float4(mp[8],  mp[9],  mp[10], mp[11]);
    }

    // -------- Phase 2: block reduce, cluster exchange, solve ----------------
#pragma unroll
    for (int i = 0; i < 16; i++) {
#pragma unroll
        for (int o = 16; o > 0; o >>= 1)
            acc[i] += __shfl_down_sync(0xffffffffu, acc[i], o);
    }

    __shared__ float sh[THREADS / 32][16];
    __shared__ float sums[16];
    __shared__ float tot[16];
    __shared__ float prm[15];
    const int warp = threadIdx.x >> 5, lane = threadIdx.x & 31;
    if (lane == 0) {
#pragma unroll
        for (int i = 0; i < 16; i++) sh[warp][i] = acc[i];
    }
    __syncthreads();
    if (threadIdx.x < 16) {
        float s = 0.f;
#pragma unroll
        for (int w = 0; w < THREADS / 32; w++) s += sh[w][threadIdx.x];
        sums[threadIdx.x] = s;
    }
    __syncthreads();

    // exchange partial sums across the 2-CTA cluster
    cluster.sync();
    const float* peer_sums = (const float*)cluster.map_shared_rank(sums, rank ^ 1);
    if (threadIdx.x < 16) tot[threadIdx.x] = sums[threadIdx.x] + peer_sums[threadIdx.x];
    __syncthreads();
    cluster.sync();   // peer may not exit / reuse smem until both have read

    if (threadIdx.x == 0) kabsch_solve(tot, prm);
    __syncthreads();

    const float r00 = prm[0], r01 = prm[1], r02 = prm[2];
    const float r10 = prm[3], r11 = prm[4], r12 = prm[5];
    const float r20 = prm[6], r21 = prm[7], r22 = prm[8];
    const float pc0 = prm[9], pc1 = prm[10], pc2 = prm[11];
    const float tc0 = prm[12], tc1 = prm[13], tc2 = prm[14];

    // -------- Phase 3: apply own half from SMEM, write out ------------------
    float4* __restrict__ o4 = reinterpret_cast<float4*>(out + (size_t)b * NPTS * 3);
#pragma unroll
    for (int it = 0; it < GPT; it++) {
        const int gl = it * THREADS + threadIdx.x;
        const int g  = gofs + gl;
        float4 s0 = spred[3*gl+0], s1 = spred[3*gl+1], s2 = spred[3*gl+2];

        float px[4] = {s0.x, s0.w, s1.z, s2.y};
        float py[4] = {s0.y, s1.x, s1.w, s2.z};
        float pz[4] = {s0.z, s1.y, s2.x, s2.w};
        float ox[4], oy[4], oz[4];
#pragma unroll
        for (int k = 0; k < 4; k++) {
            float cx = px[k] - pc0;
            float cy = py[k] - pc1;
            float cz = pz[k] - pc2;
            ox[k] = cx * r00 + cy * r10 + cz * r20 + tc0;
            oy[k] = cx * r01 + cy * r11 + cz * r21 + tc1;
            oz[k] = cx * r02 + cy * r12 + cz * r22 + tc2;
        }
        float4 o0 = {ox[0], oy[0], oz[0], ox[1]};
        float4 o1 = {oy[1], oz[1], ox[2], oy[2]};
        float4 o2 = {oz[2], ox[3], oy[3], oz[3]};
        __stcs(&o4[3*g+0], o0);
        __stcs(&o4[3*g+1], o1);
        __stcs(&o4[3*g+2], o2);
    }
}

// ---------------------------------------------------------------------------
extern "C" void kernel_launch(void* const* d_in, const int* in_sizes, int n_in,
                              void* d_out, int out_size) {
    const float*    pred  = (const float*)d_in[0];
    const float*    truec = (const float*)d_in[1];
    const float*    wts   = (const float*)d_in[2];
    const uint32_t* mask  = (const uint32_t*)d_in[3];
    float* out = (float*)d_out;

    cudaFuncSetAttribute(wra_fused, cudaFuncAttributeMaxDynamicSharedMemorySize, SMEM_BYTES);
    wra_fused<<<BATCH * 2, THREADS, SMEM_BYTES>>>(pred, truec, wts, mask, out);
}

// round 8
// speedup vs baseline: 1.0253x; 1.0253x over previous
#include <cuda_runtime.h>
#include <cooperative_groups.h>
#include <stdint.h>
#include <math.h>

namespace cg = cooperative_groups;

#define BATCH  256
#define NPTS   16384
#define THREADS 256
#define CSIZE  4
#define QGROUPS (NPTS / 4 / CSIZE)            // 1024 groups of 4 pts per CTA
#define GPT (QGROUPS / THREADS)               // 4 groups per thread
#define SMEM_BYTES (QGROUPS * 3 * 16)         // 49152 B staged masked pred

// ---------------------------------------------------------------------------
// FP32 3x3 Kabsch solve helpers
// ---------------------------------------------------------------------------
__device__ __forceinline__ float nrsqrt(float s) {
    float n = rsqrtf(s);
    return n * (1.5f - 0.5f * s * n * n);
}

__device__ __forceinline__ void jrotf(float S[3][3], float V[3][3], int p, int q) {
    float apq = S[p][q];
    if (fabsf(apq) < 1e-30f) return;
    float theta = (S[q][q] - S[p][p]) / (2.0f * apq);
    float t = copysignf(1.0f, theta) / (fabsf(theta) + sqrtf(theta * theta + 1.0f));
    float c = nrsqrt(t * t + 1.0f);
    float s = t * c;
    int r = 3 - p - q;
    float Spp = S[p][p], Sqq = S[q][q];
    S[p][p] = Spp - t * apq;
    S[q][q] = Sqq + t * apq;
    S[p][q] = S[q][p] = 0.0f;
    float Srp = S[r][p], Srq = S[r][q];
    S[r][p] = S[p][r] = c * Srp - s * Srq;
    S[r][q] = S[q][r] = s * Srp + c * Srq;
#pragma unroll
    for (int i = 0; i < 3; i++) {
        float vp = V[i][p], vq = V[i][q];
        V[i][p] = c * vp - s * vq;
        V[i][q] = s * vp + c * vq;
    }
}

__device__ void kabsch_solve(const float* sums, float* rt) {
    float W = sums[0];
    float invW = 1.0f / W;
    float Swp[3] = {sums[1], sums[2], sums[3]};
    float Swt[3] = {sums[4], sums[5], sums[6]};

    float A[3][3];
#pragma unroll
    for (int i = 0; i < 3; i++)
#pragma unroll
        for (int j = 0; j < 3; j++)
            A[i][j] = sums[7 + 3 * i + j] - Swt[i] * Swp[j] * invW;

    float S[3][3];
#pragma unroll
    for (int j = 0; j < 3; j++)
#pragma unroll
        for (int k = 0; k < 3; k++)
            S[j][k] = A[0][j] * A[0][k] + A[1][j] * A[1][k] + A[2][j] * A[2][k];

    float V[3][3] = {{1,0,0},{0,1,0},{0,0,1}};
#pragma unroll
    for (int sweep = 0; sweep < 12; sweep++) {
        jrotf(S, V, 0, 1);
        jrotf(S, V, 0, 2);
        jrotf(S, V, 1, 2);
    }

    float d[3] = {S[0][0], S[1][1], S[2][2]};
    int id[3] = {0, 1, 2};
    if (d[id[0]] < d[id[1]]) { int t = id[0]; id[0] = id[1]; id[1] = t; }
    if (d[id[0]] < d[id[2]]) { int t = id[0]; id[0] = id[2]; id[2] = t; }
    if (d[id[1]] < d[id[2]]) { int t = id[1]; id[1] = id[2]; id[2] = t; }

    float v1[3], v2[3], v3[3];
#pragma unroll
    for (int i = 0; i < 3; i++) { v1[i] = V[i][id[0]]; v2[i] = V[i][id[1]]; v3[i] = V[i][id[2]]; }

    float u1[3], u2[3];
#pragma unroll
    for (int i = 0; i < 3; i++) u1[i] = A[i][0]*v1[0] + A[i][1]*v1[1] + A[i][2]*v1[2];
    float n1 = nrsqrt(u1[0]*u1[0] + u1[1]*u1[1] + u1[2]*u1[2] + 1e-37f);
#pragma unroll
    for (int i = 0; i < 3; i++) u1[i] *= n1;
#pragma unroll
    for (int i = 0; i < 3; i++) u2[i] = A[i][0]*v2[0] + A[i][1]*v2[1] + A[i][2]*v2[2];
    float dp = u2[0]*u1[0] + u2[1]*u1[1] + u2[2]*u1[2];
#pragma unroll
    for (int i = 0; i < 3; i++) u2[i] -= dp * u1[i];
    float n2 = nrsqrt(u2[0]*u2[0] + u2[1]*u2[1] + u2[2]*u2[2] + 1e-37f);
#pragma unroll
    for (int i = 0; i < 3; i++) u2[i] *= n2;

    float detraw = v1[0]*(v2[1]*v3[2] - v2[2]*v3[1])
                 - v1[1]*(v2[0]*v3[2] - v2[2]*v3[0])
                 + v1[2]*(v2[0]*v3[1] - v2[1]*v3[0]);
    float detV = (detraw >= 0.0f) ? 1.0f : -1.0f;
    float u3[3] = {
        detV * (u1[1]*u2[2] - u1[2]*u2[1]),
        detV * (u1[2]*u2[0] - u1[0]*u2[2]),
        detV * (u1[0]*u2[1] - u1[1]*u2[0])
    };

#pragma unroll
    for (int i = 0; i < 3; i++)
#pragma unroll
        for (int j = 0; j < 3; j++)
            rt[3*i + j] = u1[i]*v1[j] + u2[i]*v2[j] + u3[i]*v3[j];
#pragma unroll
    for (int j = 0; j < 3; j++) rt[9  + j] = Swp[j] * invW;
#pragma unroll
    for (int i = 0; i < 3; i++) rt[12 + i] = Swt[i] * invW;
}

// ---------------------------------------------------------------------------
// Fused cluster kernel: 4 CTAs (256 thr, 48KB SMEM each) per batch.
// Each CTA streams + stages a quarter of the batch's masked pred; moment
// partials are combined across the cluster via DSMEM; each CTA solves
// (redundantly, trivial cost) and applies its own quarter from SMEM.
// ---------------------------------------------------------------------------
extern __shared__ float4 spred[];  // QGROUPS*3 float4 = 48 KB

__global__ void __launch_bounds__(THREADS, 4) __cluster_dims__(CSIZE, 1, 1)
wra_fused(
    const float* __restrict__ pred,
    const float* __restrict__ truec,
    const float* __restrict__ wts,
    const uint32_t* __restrict__ mask,
    float* __restrict__ out)
{
    cg::cluster_group cluster = cg::this_cluster();
    const int rank = (int)cluster.block_rank();    // 0..3
    const int b = blockIdx.x >> 2;                 // batch index
    const int gofs = rank * QGROUPS;               // group offset of this quarter

    const float4* __restrict__ p4 = reinterpret_cast<const float4*>(pred  + (size_t)b * NPTS * 3);
    const float4* __restrict__ t4 = reinterpret_cast<const float4*>(truec + (size_t)b * NPTS * 3);
    const float4* __restrict__ w4 = reinterpret_cast<const float4*>(wts   + (size_t)b * NPTS);
    const uint4* __restrict__ m4  = reinterpret_cast<const uint4*>(mask + (size_t)b * NPTS);

    float acc[16];
#pragma unroll
    for (int i = 0; i < 16; i++) acc[i] = 0.f;

    // -------- Phase 1: stream own quarter, accumulate, stage masked pred ---
#pragma unroll 2
    for (int it = 0; it < GPT; it++) {
        const int gl = it * THREADS + threadIdx.x;   // local group
        const int g  = gofs + gl;                    // global group
        float4 a0 = __ldcs(&p4[3*g+0]), a1 = __ldcs(&p4[3*g+1]), a2 = __ldcs(&p4[3*g+2]);
        float4 c0 = __ldcs(&t4[3*g+0]), c1 = __ldcs(&t4[3*g+1]), c2 = __ldcs(&t4[3*g+2]);
        float4 wv = __ldcs(&w4[g]);
        uint4  mv = __ldcs(&m4[g]);

        float px[4] = {a0.x, a0.w, a1.z, a2.y};
        float py[4] = {a0.y, a1.x, a1.w, a2.z};
        float pz[4] = {a0.z, a1.y, a2.x, a2.w};
        float tx[4] = {c0.x, c0.w, c1.z, c2.y};
        float ty[4] = {c0.y, c1.x, c1.w, c2.z};
        float tz[4] = {c0.z, c1.y, c2.x, c2.w};
        float ww[4] = {wv.x, wv.y, wv.z, wv.w};
        uint32_t mm[4] = {mv.x, mv.y, mv.z, mv.w};

        float mp[12];
#pragma unroll
        for (int k = 0; k < 4; k++) {
            bool mk = (mm[k] != 0u);
            float mx = mk ? px[k] : 0.f;
            float my = mk ? py[k] : 0.f;
            float mz = mk ? pz[k] : 0.f;
            mp[3*k+0] = mx; mp[3*k+1] = my; mp[3*k+2] = mz;

            float wi = mk ? ww[k] : 0.f;
            float wtx = wi * tx[k], wty = wi * ty[k], wtz = wi * tz[k];
            acc[0]  += wi;
            acc[1]  += wi * mx;
            acc[2]  += wi * my;
            acc[3]  += wi * mz;
            acc[4]  += wtx;
            acc[5]  += wty;
            acc[6]  += wtz;
            acc[7]  += wtx * mx;
            acc[8]  += wtx * my;
            acc[9]  += wtx * mz;
            acc[10] += wty * mx;
            acc[11] += wty * my;
            acc[12] += wty * mz;
            acc[13] += wtz * mx;
            acc[14] += wtz * my;
            acc[15] += wtz * mz;
        }
        spred[3*gl+0] = make_float4(mp[0],  mp[1],  mp[2],  mp[3]);
        spred[3*gl+1] = make_float4(mp[4],  mp[5],  mp[6],  mp[7]);
        spred[3*gl+2] = make_float4(mp[8],  mp[9],  mp[10], mp[11]);
    }

    // -------- Phase 2: block reduce, cluster exchange, solve ----------------
#pragma unroll
    for (int i = 0; i < 16; i++) {
#pragma unroll
        for (int o = 16; o > 0; o >>= 1)
            acc[i] += __shfl_down_sync(0xffffffffu, acc[i], o);
    }

    __shared__ float sh[THREADS / 32][16];
    __shared__ float sums[16];
    __shared__ float prm[15];
    const int warp = threadIdx.x >> 5, lane = threadIdx.x & 31;
    if (lane == 0) {
#pragma unroll
        for (int i = 0; i < 16; i++) sh[warp][i] = acc[i];
    }
    __syncthreads();
    if (threadIdx.x < 16) {
        float s = 0.f;
#pragma unroll
        for (int w = 0; w < THREADS / 32; w++) s += sh[w][threadIdx.x];
        sums[threadIdx.x] = s;
    }
    __syncthreads();

    // combine partial sums across the 4-CTA cluster via DSMEM
    cluster.sync();
    float tot16 = 0.f;
    if (threadIdx.x < 16) {
        tot16 = sums[threadIdx.x];
#pragma unroll
        for (int pr = 1; pr < CSIZE; pr++) {
            const float* peer = (const float*)cluster.map_shared_rank(sums, rank ^ pr);
            tot16 += peer[threadIdx.x];
        }
    }
    cluster.sync();   // all peers done reading before anyone proceeds/exits

    __shared__ float tot[16];
    if (threadIdx.x < 16) tot[threadIdx.x] = tot16;
    __syncthreads();
    if (threadIdx.x == 0) kabsch_solve(tot, prm);
    __syncthreads();

    const float r00 = prm[0], r01 = prm[1], r02 = prm[2];
    const float r10 = prm[3], r11 = prm[4], r12 = prm[5];
    const float r20 = prm[6], r21 = prm[7], r22 = prm[8];
    const float pc0 = prm[9], pc1 = prm[10], pc2 = prm[11];
    const float tc0 = prm[12], tc1 = prm[13], tc2 = prm[14];

    // -------- Phase 3: apply own quarter from SMEM, write out ---------------
    float4* __restrict__ o4 = reinterpret_cast<float4*>(out + (size_t)b * NPTS * 3);
#pragma unroll 2
    for (int it = 0; it < GPT; it++) {
        const int gl = it * THREADS + threadIdx.x;
        const int g  = gofs + gl;
        float4 s0 = spred[3*gl+0], s1 = spred[3*gl+1], s2 = spred[3*gl+2];

        float px[4] = {s0.x, s0.w, s1.z, s2.y};
        float py[4] = {s0.y, s1.x, s1.w, s2.z};
        float pz[4] = {s0.z, s1.y, s2.x, s2.w};
        float ox[4], oy[4], oz[4];
#pragma unroll
        for (int k = 0; k < 4; k++) {
            float cx = px[k] - pc0;
            float cy = py[k] - pc1;
            float cz = pz[k] - pc2;
            ox[k] = cx * r00 + cy * r10 + cz * r20 + tc0;
            oy[k] = cx * r01 + cy * r11 + cz * r21 + tc1;
            oz[k] = cx * r02 + cy * r12 + cz * r22 + tc2;
        }
        float4 o0 = {ox[0], oy[0], oz[0], ox[1]};
        float4 o1 = {oy[1], oz[1], ox[2], oy[2]};
        float4 o2 = {oz[2], ox[3], oy[3], oz[3]};
        __stcs(&o4[3*g+0], o0);
        __stcs(&o4[3*g+1], o1);
        __stcs(&o4[3*g+2], o2);
    }
}

// ---------------------------------------------------------------------------
extern "C" void kernel_launch(void* const* d_in, const int* in_sizes, int n_in,
                              void* d_out, int out_size) {
    const float*    pred  = (const float*)d_in[0];
    const float*    truec = (const float*)d_in[1];
    const float*    wts   = (const float*)d_in[2];
    const uint32_t* mask  = (const uint32_t*)d_in[3];
    float* out = (float*)d_out;

    cudaFuncSetAttribute(wra_fused, cudaFuncAttributeMaxDynamicSharedMemorySize, SMEM_BYTES);
    wra_fused<<<BATCH * CSIZE, THREADS, SMEM_BYTES>>>(pred, truec, wts, mask, out);
}

// round 9
// speedup vs baseline: 1.3884x; 1.3542x over previous
#include <cuda_runtime.h>
#include <stdint.h>
#include <math.h>

#define BATCH  256
#define NPTS   16384
#define CHUNKS 2
#define GRP_PER_CHUNK (NPTS / 4 / CHUNKS)   // 2048 groups of 4 points
#define RED_THREADS 256

// scratch: per-batch partial sums and solved transform params
__device__ float g_part[BATCH][CHUNKS][16]; // [0]=W,[1:4]=S(w*p),[4:7]=S(w*t),[7:16]=M[i][j]=S(w*t_i*p_j)
__device__ float g_rt[BATCH][16];           // [0:9]=rot row-major, [9:12]=pred centroid, [12:15]=true centroid

// ---------------------------------------------------------------------------
// Kernel 1: grid (CHUNKS=2, BATCH) x 256 threads = 512 blocks, one wave at
// 4 CTAs/SM. unroll-4 so ptxas can front-batch ~2 iterations of loads.
// ---------------------------------------------------------------------------
__global__ void __launch_bounds__(RED_THREADS, 4) wra_reduce(
    const float* __restrict__ pred,
    const float* __restrict__ truec,
    const float* __restrict__ wts,
    const uint32_t* __restrict__ mask)
{
    const int b = blockIdx.y;
    const int chunk = blockIdx.x;
    const float4* __restrict__ p4 = reinterpret_cast<const float4*>(pred  + (size_t)b * NPTS * 3);
    const float4* __restrict__ t4 = reinterpret_cast<const float4*>(truec + (size_t)b * NPTS * 3);
    const float4* __restrict__ w4 = reinterpret_cast<const float4*>(wts   + (size_t)b * NPTS);
    const uint4* __restrict__ m4  = reinterpret_cast<const uint4*>(mask + (size_t)b * NPTS);

    float acc[16];
#pragma unroll
    for (int i = 0; i < 16; i++) acc[i] = 0.f;

    const int g0 = chunk * GRP_PER_CHUNK;
#pragma unroll 4
    for (int it = 0; it < GRP_PER_CHUNK / RED_THREADS; it++) {
        const int g = g0 + it * RED_THREADS + threadIdx.x;
        float4 a0 = __ldg(&p4[3*g+0]), a1 = __ldg(&p4[3*g+1]), a2 = __ldg(&p4[3*g+2]);
        float4 c0 = __ldcs(&t4[3*g+0]), c1 = __ldcs(&t4[3*g+1]), c2 = __ldcs(&t4[3*g+2]);
        float4 wv = __ldcs(&w4[g]);
        uint4  mv = __ldg(&m4[g]);

        float px[4] = {a0.x, a0.w, a1.z, a2.y};
        float py[4] = {a0.y, a1.x, a1.w, a2.z};
        float pz[4] = {a0.z, a1.y, a2.x, a2.w};
        float tx[4] = {c0.x, c0.w, c1.z, c2.y};
        float ty[4] = {c0.y, c1.x, c1.w, c2.z};
        float tz[4] = {c0.z, c1.y, c2.x, c2.w};
        float ww[4] = {wv.x, wv.y, wv.z, wv.w};
        uint32_t mm[4] = {mv.x, mv.y, mv.z, mv.w};

#pragma unroll
        for (int k = 0; k < 4; k++) {
            float wi = (mm[k] != 0u) ? ww[k] : 0.f;
            float wtx = wi * tx[k], wty = wi * ty[k], wtz = wi * tz[k];
            acc[0]  += wi;
            acc[1]  += wi * px[k];
            acc[2]  += wi * py[k];
            acc[3]  += wi * pz[k];
            acc[4]  += wtx;
            acc[5]  += wty;
            acc[6]  += wtz;
            acc[7]  += wtx * px[k];
            acc[8]  += wtx * py[k];
            acc[9]  += wtx * pz[k];
            acc[10] += wty * px[k];
            acc[11] += wty * py[k];
            acc[12] += wty * pz[k];
            acc[13] += wtz * px[k];
            acc[14] += wtz * py[k];
            acc[15] += wtz * pz[k];
        }
    }

    // warp tree-reduce each accumulator
#pragma unroll
    for (int i = 0; i < 16; i++) {
#pragma unroll
        for (int o = 16; o > 0; o >>= 1)
            acc[i] += __shfl_down_sync(0xffffffffu, acc[i], o);
    }

    __shared__ float sh[RED_THREADS / 32][16];
    const int warp = threadIdx.x >> 5, lane = threadIdx.x & 31;
    if (lane == 0) {
#pragma unroll
        for (int i = 0; i < 16; i++) sh[warp][i] = acc[i];
    }
    __syncthreads();
    if (threadIdx.x < 16) {
        float s = 0.f;
#pragma unroll
        for (int w = 0; w < RED_THREADS / 32; w++) s += sh[w][threadIdx.x];
        g_part[b][chunk][threadIdx.x] = s;
    }
}

// ---------------------------------------------------------------------------
// Kernel 2: per-batch 3x3 Kabsch solve, FP32, one thread per batch over 8 SMs.
// ---------------------------------------------------------------------------
__device__ __forceinline__ float nrsqrt(float s) {
    float n = rsqrtf(s);
    return n * (1.5f - 0.5f * s * n * n);   // one Newton step
}

__device__ __forceinline__ void jrotf(float S[3][3], float V[3][3], int p, int q) {
    float apq = S[p][q];
    if (fabsf(apq) < 1e-30f) return;
    float theta = (S[q][q] - S[p][p]) / (2.0f * apq);
    float t = copysignf(1.0f, theta) / (fabsf(theta) + sqrtf(theta * theta + 1.0f));
    float c = nrsqrt(t * t + 1.0f);
    float s = t * c;
    int r = 3 - p - q;
    float Spp = S[p][p], Sqq = S[q][q];
    S[p][p] = Spp - t * apq;
    S[q][q] = Sqq + t * apq;
    S[p][q] = S[q][p] = 0.0f;
    float Srp = S[r][p], Srq = S[r][q];
    S[r][p] = S[p][r] = c * Srp - s * Srq;
    S[r][q] = S[q][r] = s * Srp + c * Srq;
#pragma unroll
    for (int i = 0; i < 3; i++) {
        float vp = V[i][p], vq = V[i][q];
        V[i][p] = c * vp - s * vq;
        V[i][q] = s * vp + c * vq;
    }
}

__global__ void wra_solve() {
    const int b = blockIdx.x * blockDim.x + threadIdx.x;
    if (b >= BATCH) return;

    float sums[16];
#pragma unroll
    for (int i = 0; i < 16; i++) {
        float s = 0.f;
#pragma unroll
        for (int c = 0; c < CHUNKS; c++) s += g_part[b][c][i];
        sums[i] = s;
    }

    float W = sums[0];
    float invW = 1.0f / W;
    float Swp[3] = {sums[1], sums[2], sums[3]};
    float Swt[3] = {sums[4], sums[5], sums[6]};

    float A[3][3];  // cov[i][j] = M[i][j] - Swt_i * Swp_j / W
#pragma unroll
    for (int i = 0; i < 3; i++)
#pragma unroll
        for (int j = 0; j < 3; j++)
            A[i][j] = sums[7 + 3 * i + j] - Swt[i] * Swp[j] * invW;

    float S[3][3];
#pragma unroll
    for (int j = 0; j < 3; j++)
#pragma unroll
        for (int k = 0; k < 3; k++)
            S[j][k] = A[0][j] * A[0][k] + A[1][j] * A[1][k] + A[2][j] * A[2][k];

    float V[3][3] = {{1,0,0},{0,1,0},{0,0,1}};
#pragma unroll
    for (int sweep = 0; sweep < 12; sweep++) {
        jrotf(S, V, 0, 1);
        jrotf(S, V, 0, 2);
        jrotf(S, V, 1, 2);
    }

    float d[3] = {S[0][0], S[1][1], S[2][2]};
    int id[3] = {0, 1, 2};
    if (d[id[0]] < d[id[1]]) { int t = id[0]; id[0] = id[1]; id[1] = t; }
    if (d[id[0]] < d[id[2]]) { int t = id[0]; id[0] = id[2]; id[2] = t; }
    if (d[id[1]] < d[id[2]]) { int t = id[1]; id[1] = id[2]; id[2] = t; }

    float v1[3], v2[3], v3[3];
#pragma unroll
    for (int i = 0; i < 3; i++) { v1[i] = V[i][id[0]]; v2[i] = V[i][id[1]]; v3[i] = V[i][id[2]]; }

    float u1[3], u2[3];
#pragma unroll
    for (int i = 0; i < 3; i++) u1[i] = A[i][0]*v1[0] + A[i][1]*v1[1] + A[i][2]*v1[2];
    float n1 = nrsqrt(u1[0]*u1[0] + u1[1]*u1[1] + u1[2]*u1[2] + 1e-37f);
#pragma unroll
    for (int i = 0; i < 3; i++) u1[i] *= n1;
#pragma unroll
    for (int i = 0; i < 3; i++) u2[i] = A[i][0]*v2[0] + A[i][1]*v2[1] + A[i][2]*v2[2];
    float dp = u2[0]*u1[0] + u2[1]*u1[1] + u2[2]*u1[2];
#pragma unroll
    for (int i = 0; i < 3; i++) u2[i] -= dp * u1[i];
    float n2 = nrsqrt(u2[0]*u2[0] + u2[1]*u2[1] + u2[2]*u2[2] + 1e-37f);
#pragma unroll
    for (int i = 0; i < 3; i++) u2[i] *= n2;

    float detraw = v1[0]*(v2[1]*v3[2] - v2[2]*v3[1])
                 - v1[1]*(v2[0]*v3[2] - v2[2]*v3[0])
                 + v1[2]*(v2[0]*v3[1] - v2[1]*v3[0]);
    float detV = (detraw >= 0.0f) ? 1.0f : -1.0f;
    float u3[3] = {
        detV * (u1[1]*u2[2] - u1[2]*u2[1]),
        detV * (u1[2]*u2[0] - u1[0]*u2[2]),
        detV * (u1[0]*u2[1] - u1[1]*u2[0])
    };

#pragma unroll
    for (int i = 0; i < 3; i++)
#pragma unroll
        for (int j = 0; j < 3; j++)
            g_rt[b][3*i + j] = u1[i]*v1[j] + u2[i]*v2[j] + u3[i]*v3[j];
#pragma unroll
    for (int j = 0; j < 3; j++) g_rt[b][9  + j] = Swp[j] * invW;
#pragma unroll
    for (int i = 0; i < 3; i++) g_rt[b][12 + i] = Swt[i] * invW;
    g_rt[b][15] = 0.f;
}

// ---------------------------------------------------------------------------
// Kernel 3: apply  out = ((mask?pred:0) - pc) @ R + tc
// 2 groups per thread (8 independent 16B loads in flight), reverse batch order.
// ---------------------------------------------------------------------------
#define APPLY_GPT 2
#define APPLY_THREADS 256
#define APPLY_BLKX ((NPTS / 4) / (APPLY_THREADS * APPLY_GPT))   // 8

__global__ void __launch_bounds__(APPLY_THREADS, 4) wra_apply(
    const float* __restrict__ pred,
    const uint32_t* __restrict__ mask,
    float* __restrict__ out)
{
    const int b = BATCH - 1 - blockIdx.y;   // reverse batch order (L2 recency)
    __shared__ float prm[15];
    if (threadIdx.x < 15) prm[threadIdx.x] = g_rt[b][threadIdx.x];
    __syncthreads();
    const float r00 = prm[0], r01 = prm[1], r02 = prm[2];
    const float r10 = prm[3], r11 = prm[4], r12 = prm[5];
    const float r20 = prm[6], r21 = prm[7], r22 = prm[8];
    const float pc0 = prm[9], pc1 = prm[10], pc2 = prm[11];
    const float tc0 = prm[12], tc1 = prm[13], tc2 = prm[14];

    const float4* __restrict__ p4 = reinterpret_cast<const float4*>(pred + (size_t)b * NPTS * 3);
    float4* __restrict__ o4 = reinterpret_cast<float4*>(out + (size_t)b * NPTS * 3);
    const uint4* __restrict__ m4 = reinterpret_cast<const uint4*>(mask + (size_t)b * NPTS);

    const int gbase = blockIdx.x * (APPLY_THREADS * APPLY_GPT) + threadIdx.x;

    // Load both groups' payload up front (8 independent 16B loads)
    float4 A0[APPLY_GPT], A1[APPLY_GPT], A2[APPLY_GPT];
    uint4  MV[APPLY_GPT];
#pragma unroll
    for (int j = 0; j < APPLY_GPT; j++) {
        const int g = gbase + j * APPLY_THREADS;
        A0[j] = __ldg(&p4[3*g+0]);
        A1[j] = __ldg(&p4[3*g+1]);
        A2[j] = __ldg(&p4[3*g+2]);
        MV[j] = __ldg(&m4[g]);
    }

#pragma unroll
    for (int j = 0; j < APPLY_GPT; j++) {
        const int g = gbase + j * APPLY_THREADS;
        float px[4] = {A0[j].x, A0[j].w, A1[j].z, A2[j].y};
        float py[4] = {A0[j].y, A1[j].x, A1[j].w, A2[j].z};
        float pz[4] = {A0[j].z, A1[j].y, A2[j].x, A2[j].w};
        uint32_t mm[4] = {MV[j].x, MV[j].y, MV[j].z, MV[j].w};
        float ox[4], oy[4], oz[4];
#pragma unroll
        for (int k = 0; k < 4; k++) {
            bool mk = (mm[k] != 0u);
            float cx = (mk ? px[k] : 0.f) - pc0;
            float cy = (mk ? py[k] : 0.f) - pc1;
            float cz = (mk ? pz[k] : 0.f) - pc2;
            ox[k] = cx * r00 + cy * r10 + cz * r20 + tc0;
            oy[k] = cx * r01 + cy * r11 + cz * r21 + tc1;
            oz[k] = cx * r02 + cy * r12 + cz * r22 + tc2;
        }
        float4 o0 = {ox[0], oy[0], oz[0], ox[1]};
        float4 o1 = {oy[1], oz[1], ox[2], oy[2]};
        float4 o2 = {oz[2], ox[3], oy[3], oz[3]};
        __stcs(&o4[3*g+0], o0);
        __stcs(&o4[3*g+1], o1);
        __stcs(&o4[3*g+2], o2);
    }
}

// ---------------------------------------------------------------------------
extern "C" void kernel_launch(void* const* d_in, const int* in_sizes, int n_in,
                              void* d_out, int out_size) {
    const float*    pred  = (const float*)d_in[0];
    const float*    truec = (const float*)d_in[1];
    const float*    wts   = (const float*)d_in[2];
    const uint32_t* mask  = (const uint32_t*)d_in[3];
    float* out = (float*)d_out;

    wra_reduce<<<dim3(CHUNKS, BATCH), RED_THREADS>>>(pred, truec, wts, mask);
    wra_solve<<<8, 32>>>();
    wra_apply<<<dim3(APPLY_BLKX, BATCH), APPLY_THREADS>>>(pred, mask, out);
}

// round 10
// speedup vs baseline: 1.4448x; 1.0406x over previous
#include <cuda_runtime.h>
#include <stdint.h>
#include <math.h>

#define BATCH  256
#define NPTS   16384
#define CHUNKS 2
#define GRP_PER_CHUNK (NPTS / 4 / CHUNKS)   // 2048 groups of 4 points
#define RED_THREADS 256

// scratch: per-batch partial sums, completion counters, solved transforms
__device__ float g_part[BATCH][CHUNKS][16];
__device__ unsigned g_cnt[BATCH];           // zero-init; reset in-kernel each run
__device__ float g_rt[BATCH][16];           // [0:9]=rot, [9:12]=pred centroid, [12:15]=true centroid

// ---------------------------------------------------------------------------
// FP32 3x3 Kabsch solve
// ---------------------------------------------------------------------------
__device__ __forceinline__ float nrsqrt(float s) {
    float n = rsqrtf(s);
    return n * (1.5f - 0.5f * s * n * n);   // one Newton step
}

__device__ __forceinline__ void jrotf(float S[3][3], float V[3][3], int p, int q) {
    float apq = S[p][q];
    if (fabsf(apq) < 1e-30f) return;
    float theta = (S[q][q] - S[p][p]) / (2.0f * apq);
    float t = copysignf(1.0f, theta) / (fabsf(theta) + sqrtf(theta * theta + 1.0f));
    float c = nrsqrt(t * t + 1.0f);
    float s = t * c;
    int r = 3 - p - q;
    float Spp = S[p][p], Sqq = S[q][q];
    S[p][p] = Spp - t * apq;
    S[q][q] = Sqq + t * apq;
    S[p][q] = S[q][p] = 0.0f;
    float Srp = S[r][p], Srq = S[r][q];
    S[r][p] = S[p][r] = c * Srp - s * Srq;
    S[r][q] = S[q][r] = s * Srp + c * Srq;
#pragma unroll
    for (int i = 0; i < 3; i++) {
        float vp = V[i][p], vq = V[i][q];
        V[i][p] = c * vp - s * vq;
        V[i][q] = s * vp + c * vq;
    }
}

__device__ void kabsch_solve(const float* sums, float* rt) {
    float W = sums[0];
    float invW = 1.0f / W;
    float Swp[3] = {sums[1], sums[2], sums[3]};
    float Swt[3] = {sums[4], sums[5], sums[6]};

    float A[3][3];  // cov[i][j] = M[i][j] - Swt_i * Swp_j / W
#pragma unroll
    for (int i = 0; i < 3; i++)
#pragma unroll
        for (int j = 0; j < 3; j++)
            A[i][j] = sums[7 + 3 * i + j] - Swt[i] * Swp[j] * invW;

    float S[3][3];
#pragma unroll
    for (int j = 0; j < 3; j++)
#pragma unroll
        for (int k = 0; k < 3; k++)
            S[j][k] = A[0][j] * A[0][k] + A[1][j] * A[1][k] + A[2][j] * A[2][k];

    float V[3][3] = {{1,0,0},{0,1,0},{0,0,1}};
#pragma unroll
    for (int sweep = 0; sweep < 12; sweep++) {
        jrotf(S, V, 0, 1);
        jrotf(S, V, 0, 2);
        jrotf(S, V, 1, 2);
    }

    float d[3] = {S[0][0], S[1][1], S[2][2]};
    int id[3] = {0, 1, 2};
    if (d[id[0]] < d[id[1]]) { int t = id[0]; id[0] = id[1]; id[1] = t; }
    if (d[id[0]] < d[id[2]]) { int t = id[0]; id[0] = id[2]; id[2] = t; }
    if (d[id[1]] < d[id[2]]) { int t = id[1]; id[1] = id[2]; id[2] = t; }

    float v1[3], v2[3], v3[3];
#pragma unroll
    for (int i = 0; i < 3; i++) { v1[i] = V[i][id[0]]; v2[i] = V[i][id[1]]; v3[i] = V[i][id[2]]; }

    float u1[3], u2[3];
#pragma unroll
    for (int i = 0; i < 3; i++) u1[i] = A[i][0]*v1[0] + A[i][1]*v1[1] + A[i][2]*v1[2];
    float n1 = nrsqrt(u1[0]*u1[0] + u1[1]*u1[1] + u1[2]*u1[2] + 1e-37f);
#pragma unroll
    for (int i = 0; i < 3; i++) u1[i] *= n1;
#pragma unroll
    for (int i = 0; i < 3; i++) u2[i] = A[i][0]*v2[0] + A[i][1]*v2[1] + A[i][2]*v2[2];
    float dp = u2[0]*u1[0] + u2[1]*u1[1] + u2[2]*u1[2];
#pragma unroll
    for (int i = 0; i < 3; i++) u2[i] -= dp * u1[i];
    float n2 = nrsqrt(u2[0]*u2[0] + u2[1]*u2[1] + u2[2]*u2[2] + 1e-37f);
#pragma unroll
    for (int i = 0; i < 3; i++) u2[i] *= n2;

    float detraw = v1[0]*(v2[1]*v3[2] - v2[2]*v3[1])
                 - v1[1]*(v2[0]*v3[2] - v2[2]*v3[0])
                 + v1[2]*(v2[0]*v3[1] - v2[1]*v3[0]);
    float detV = (detraw >= 0.0f) ? 1.0f : -1.0f;
    float u3[3] = {
        detV * (u1[1]*u2[2] - u1[2]*u2[1]),
        detV * (u1[2]*u2[0] - u1[0]*u2[2]),
        detV * (u1[0]*u2[1] - u1[1]*u2[0])
    };

#pragma unroll
    for (int i = 0; i < 3; i++)
#pragma unroll
        for (int j = 0; j < 3; j++)
            rt[3*i + j] = u1[i]*v1[j] + u2[i]*v2[j] + u3[i]*v3[j];
#pragma unroll
    for (int j = 0; j < 3; j++) rt[9  + j] = Swp[j] * invW;
#pragma unroll
    for (int i = 0; i < 3; i++) rt[12 + i] = Swt[i] * invW;
}

// ---------------------------------------------------------------------------
// Kernel 1: partial moment reduction; per-batch LAST chunk block also runs
// the 3x3 solve (fence + atomic counter), hiding solve under other batches'
// streaming. Counter is reset in-kernel for graph-replay determinism.
// ---------------------------------------------------------------------------
__global__ void __launch_bounds__(RED_THREADS, 4) wra_reduce(
    const float* __restrict__ pred,
    const float* __restrict__ truec,
    const float* __restrict__ wts,
    const uint32_t* __restrict__ mask)
{
    const int b = blockIdx.y;
    const int chunk = blockIdx.x;
    const float4* __restrict__ p4 = reinterpret_cast<const float4*>(pred  + (size_t)b * NPTS * 3);
    const float4* __restrict__ t4 = reinterpret_cast<const float4*>(truec + (size_t)b * NPTS * 3);
    const float4* __restrict__ w4 = reinterpret_cast<const float4*>(wts   + (size_t)b * NPTS);
    const uint4* __restrict__ m4  = reinterpret_cast<const uint4*>(mask + (size_t)b * NPTS);

    float acc[16];
#pragma unroll
    for (int i = 0; i < 16; i++) acc[i] = 0.f;

    const int g0 = chunk * GRP_PER_CHUNK;
#pragma unroll
    for (int it = 0; it < GRP_PER_CHUNK / RED_THREADS; it++) {
        const int g = g0 + it * RED_THREADS + threadIdx.x;
        float4 a0 = __ldg(&p4[3*g+0]), a1 = __ldg(&p4[3*g+1]), a2 = __ldg(&p4[3*g+2]);
        float4 c0 = __ldcs(&t4[3*g+0]), c1 = __ldcs(&t4[3*g+1]), c2 = __ldcs(&t4[3*g+2]);
        float4 wv = __ldcs(&w4[g]);
        uint4  mv = __ldg(&m4[g]);

        float px[4] = {a0.x, a0.w, a1.z, a2.y};
        float py[4] = {a0.y, a1.x, a1.w, a2.z};
        float pz[4] = {a0.z, a1.y, a2.x, a2.w};
        float tx[4] = {c0.x, c0.w, c1.z, c2.y};
        float ty[4] = {c0.y, c1.x, c1.w, c2.z};
        float tz[4] = {c0.z, c1.y, c2.x, c2.w};
        float ww[4] = {wv.x, wv.y, wv.z, wv.w};
        uint32_t mm[4] = {mv.x, mv.y, mv.z, mv.w};

#pragma unroll
        for (int k = 0; k < 4; k++) {
            float wi = (mm[k] != 0u) ? ww[k] : 0.f;
            float wtx = wi * tx[k], wty = wi * ty[k], wtz = wi * tz[k];
            acc[0]  += wi;
            acc[1]  += wi * px[k];
            acc[2]  += wi * py[k];
            acc[3]  += wi * pz[k];
            acc[4]  += wtx;
            acc[5]  += wty;
            acc[6]  += wtz;
            acc[7]  += wtx * px[k];
            acc[8]  += wtx * py[k];
            acc[9]  += wtx * pz[k];
            acc[10] += wty * px[k];
            acc[11] += wty * py[k];
            acc[12] += wty * pz[k];
            acc[13] += wtz * px[k];
            acc[14] += wtz * py[k];
            acc[15] += wtz * pz[k];
        }
    }

    // warp tree-reduce each accumulator
#pragma unroll
    for (int i = 0; i < 16; i++) {
#pragma unroll
        for (int o = 16; o > 0; o >>= 1)
            acc[i] += __shfl_down_sync(0xffffffffu, acc[i], o);
    }

    __shared__ float sh[RED_THREADS / 32][16];
    const int warp = threadIdx.x >> 5, lane = threadIdx.x & 31;
    if (lane == 0) {
#pragma unroll
        for (int i = 0; i < 16; i++) sh[warp][i] = acc[i];
    }
    __syncthreads();
    if (threadIdx.x < 16) {
        float s = 0.f;
#pragma unroll
        for (int w = 0; w < RED_THREADS / 32; w++) s += sh[w][threadIdx.x];
        g_part[b][chunk][threadIdx.x] = s;
    }
    __syncthreads();

    // last-arriving chunk block of this batch performs the solve
    if (threadIdx.x == 0) {
        __threadfence();                                  // publish g_part
        unsigned prev = atomicAdd(&g_cnt[b], 1u);
        if (prev == CHUNKS - 1) {
            __threadfence();                              // acquire peers' g_part
            float sums[16];
#pragma unroll
            for (int i = 0; i < 16; i++) {
                float s = 0.f;
#pragma unroll
                for (int c = 0; c < CHUNKS; c++) s += g_part[b][c][i];
                sums[i] = s;
            }
            float rt[15];
            kabsch_solve(sums, rt);
#pragma unroll
            for (int i = 0; i < 15; i++) g_rt[b][i] = rt[i];
            g_cnt[b] = 0u;                                // reset for next replay
        }
    }
}

// ---------------------------------------------------------------------------
// Kernel 2: apply  out = ((mask?pred:0) - pc) @ R + tc
// ---------------------------------------------------------------------------
#define APPLY_GPT 2
#define APPLY_THREADS 256
#define APPLY_BLKX ((NPTS / 4) / (APPLY_THREADS * APPLY_GPT))   // 8

__global__ void __launch_bounds__(APPLY_THREADS, 4) wra_apply(
    const float* __restrict__ pred,
    const uint32_t* __restrict__ mask,
    float* __restrict__ out)
{
    const int b = BATCH - 1 - blockIdx.y;   // reverse batch order (L2 recency)
    __shared__ float prm[15];
    if (threadIdx.x < 15) prm[threadIdx.x] = g_rt[b][threadIdx.x];
    __syncthreads();
    const float r00 = prm[0], r01 = prm[1], r02 = prm[2];
    const float r10 = prm[3], r11 = prm[4], r12 = prm[5];
    const float r20 = prm[6], r21 = prm[7], r22 = prm[8];
    const float pc0 = prm[9], pc1 = prm[10], pc2 = prm[11];
    const float tc0 = prm[12], tc1 = prm[13], tc2 = prm[14];

    const float4* __restrict__ p4 = reinterpret_cast<const float4*>(pred + (size_t)b * NPTS * 3);
    float4* __restrict__ o4 = reinterpret_cast<float4*>(out + (size_t)b * NPTS * 3);
    const uint4* __restrict__ m4 = reinterpret_cast<const uint4*>(mask + (size_t)b * NPTS);

    const int gbase = blockIdx.x * (APPLY_THREADS * APPLY_GPT) + threadIdx.x;

    float4 A0[APPLY_GPT], A1[APPLY_GPT], A2[APPLY_GPT];
    uint4  MV[APPLY_GPT];
#pragma unroll
    for (int j = 0; j < APPLY_GPT; j++) {
        const int g = gbase + j * APPLY_THREADS;
        A0[j] = __ldg(&p4[3*g+0]);
        A1[j] = __ldg(&p4[3*g+1]);
        A2[j] = __ldg(&p4[3*g+2]);
        MV[j] = __ldg(&m4[g]);
    }

#pragma unroll
    for (int j = 0; j < APPLY_GPT; j++) {
        const int g = gbase + j * APPLY_THREADS;
        float px[4] = {A0[j].x, A0[j].w, A1[j].z, A2[j].y};
        float py[4] = {A0[j].y, A1[j].x, A1[j].w, A2[j].z};
        float pz[4] = {A0[j].z, A1[j].y, A2[j].x, A2[j].w};
        uint32_t mm[4] = {MV[j].x, MV[j].y, MV[j].z, MV[j].w};
        float ox[4], oy[4], oz[4];
#pragma unroll
        for (int k = 0; k < 4; k++) {
            bool mk = (mm[k] != 0u);
            float cx = (mk ? px[k] : 0.f) - pc0;
            float cy = (mk ? py[k] : 0.f) - pc1;
            float cz = (mk ? pz[k] : 0.f) - pc2;
            ox[k] = cx * r00 + cy * r10 + cz * r20 + tc0;
            oy[k] = cx * r01 + cy * r11 + cz * r21 + tc1;
            oz[k] = cx * r02 + cy * r12 + cz * r22 + tc2;
        }
        float4 o0 = {ox[0], oy[0], oz[0], ox[1]};
        float4 o1 = {oy[1], oz[1], ox[2], oy[2]};
        float4 o2 = {oz[2], ox[3], oy[3], oz[3]};
        __stcs(&o4[3*g+0], o0);
        __stcs(&o4[3*g+1], o1);
        __stcs(&o4[3*g+2], o2);
    }
}

// ---------------------------------------------------------------------------
extern "C" void kernel_launch(void* const* d_in, const int* in_sizes, int n_in,
                              void* d_out, int out_size) {
    const float*    pred  = (const float*)d_in[0];
    const float*    truec = (const float*)d_in[1];
    const float*    wts   = (const float*)d_in[2];
    const uint32_t* mask  = (const uint32_t*)d_in[3];
    float* out = (float*)d_out;

    wra_reduce<<<dim3(CHUNKS, BATCH), RED_THREADS>>>(pred, truec, wts, mask);
    wra_apply<<<dim3(APPLY_BLKX, BATCH), APPLY_THREADS>>>(pred, mask, out);
}

// round 11
// speedup vs baseline: 1.4508x; 1.0042x over previous
#include <cuda_runtime.h>
#include <stdint.h>
#include <math.h>

#define BATCH  256
#define NPTS   16384
#define CHUNKS 2
#define GRP_PER_CHUNK (NPTS / 4 / CHUNKS)   // 2048 groups of 4 points
#define RED_THREADS 256

// scratch: per-batch partial sums, completion counters, solved transforms
__device__ float g_part[BATCH][CHUNKS][16];
__device__ unsigned g_cnt[BATCH];           // zero-init; reset in-kernel each run
__device__ float g_rt[BATCH][16];           // [0:9]=rot, [9:12]=pred centroid, [12:15]=true centroid

// ---------------------------------------------------------------------------
// FP32 3x3 Kabsch solve
// ---------------------------------------------------------------------------
__device__ __forceinline__ float nrsqrt(float s) {
    float n = rsqrtf(s);
    return n * (1.5f - 0.5f * s * n * n);   // one Newton step
}

__device__ __forceinline__ void jrotf(float S[3][3], float V[3][3], int p, int q) {
    float apq = S[p][q];
    if (fabsf(apq) < 1e-30f) return;
    float theta = (S[q][q] - S[p][p]) / (2.0f * apq);
    float t = copysignf(1.0f, theta) / (fabsf(theta) + sqrtf(theta * theta + 1.0f));
    float c = nrsqrt(t * t + 1.0f);
    float s = t * c;
    int r = 3 - p - q;
    float Spp = S[p][p], Sqq = S[q][q];
    S[p][p] = Spp - t * apq;
    S[q][q] = Sqq + t * apq;
    S[p][q] = S[q][p] = 0.0f;
    float Srp = S[r][p], Srq = S[r][q];
    S[r][p] = S[p][r] = c * Srp - s * Srq;
    S[r][q] = S[q][r] = s * Srp + c * Srq;
#pragma unroll
    for (int i = 0; i < 3; i++) {
        float vp = V[i][p], vq = V[i][q];
        V[i][p] = c * vp - s * vq;
        V[i][q] = s * vp + c * vq;
    }
}

__device__ void kabsch_solve(const float* sums, float* rt) {
    float W = sums[0];
    float invW = 1.0f / W;
    float Swp[3] = {sums[1], sums[2], sums[3]};
    float Swt[3] = {sums[4], sums[5], sums[6]};

    float A[3][3];  // cov[i][j] = M[i][j] - Swt_i * Swp_j / W
#pragma unroll
    for (int i = 0; i < 3; i++)
#pragma unroll
        for (int j = 0; j < 3; j++)
            A[i][j] = sums[7 + 3 * i + j] - Swt[i] * Swp[j] * invW;

    float S[3][3];
#pragma unroll
    for (int j = 0; j < 3; j++)
#pragma unroll
        for (int k = 0; k < 3; k++)
            S[j][k] = A[0][j] * A[0][k] + A[1][j] * A[1][k] + A[2][j] * A[2][k];

    float V[3][3] = {{1,0,0},{0,1,0},{0,0,1}};
#pragma unroll
    for (int sweep = 0; sweep < 12; sweep++) {
        jrotf(S, V, 0, 1);
        jrotf(S, V, 0, 2);
        jrotf(S, V, 1, 2);
    }

    float d[3] = {S[0][0], S[1][1], S[2][2]};
    int id[3] = {0, 1, 2};
    if (d[id[0]] < d[id[1]]) { int t = id[0]; id[0] = id[1]; id[1] = t; }
    if (d[id[0]] < d[id[2]]) { int t = id[0]; id[0] = id[2]; id[2] = t; }
    if (d[id[1]] < d[id[2]]) { int t = id[1]; id[1] = id[2]; id[2] = t; }

    float v1[3], v2[3], v3[3];
#pragma unroll
    for (int i = 0; i < 3; i++) { v1[i] = V[i][id[0]]; v2[i] = V[i][id[1]]; v3[i] = V[i][id[2]]; }

    float u1[3], u2[3];
#pragma unroll
    for (int i = 0; i < 3; i++) u1[i] = A[i][0]*v1[0] + A[i][1]*v1[1] + A[i][2]*v1[2];
    float n1 = nrsqrt(u1[0]*u1[0] + u1[1]*u1[1] + u1[2]*u1[2] + 1e-37f);
#pragma unroll
    for (int i = 0; i < 3; i++) u1[i] *= n1;
#pragma unroll
    for (int i = 0; i < 3; i++) u2[i] = A[i][0]*v2[0] + A[i][1]*v2[1] + A[i][2]*v2[2];
    float dp = u2[0]*u1[0] + u2[1]*u1[1] + u2[2]*u1[2];
#pragma unroll
    for (int i = 0; i < 3; i++) u2[i] -= dp * u1[i];
    float n2 = nrsqrt(u2[0]*u2[0] + u2[1]*u2[1] + u2[2]*u2[2] + 1e-37f);
#pragma unroll
    for (int i = 0; i < 3; i++) u2[i] *= n2;

    float detraw = v1[0]*(v2[1]*v3[2] - v2[2]*v3[1])
                 - v1[1]*(v2[0]*v3[2] - v2[2]*v3[0])
                 + v1[2]*(v2[0]*v3[1] - v2[1]*v3[0]);
    float detV = (detraw >= 0.0f) ? 1.0f : -1.0f;
    float u3[3] = {
        detV * (u1[1]*u2[2] - u1[2]*u2[1]),
        detV * (u1[2]*u2[0] - u1[0]*u2[2]),
        detV * (u1[0]*u2[1] - u1[1]*u2[0])
    };

#pragma unroll
    for (int i = 0; i < 3; i++)
#pragma unroll
        for (int j = 0; j < 3; j++)
            rt[3*i + j] = u1[i]*v1[j] + u2[i]*v2[j] + u3[i]*v3[j];
#pragma unroll
    for (int j = 0; j < 3; j++) rt[9  + j] = Swp[j] * invW;
#pragma unroll
    for (int i = 0; i < 3; i++) rt[12 + i] = Swt[i] * invW;
}

// ---------------------------------------------------------------------------
// Kernel 1: partial moment reduction; per-batch LAST chunk block also runs
// the 3x3 solve (fence + atomic counter), hiding the solve under other
// batches' streaming. Counter reset in-kernel for graph-replay determinism.
// ---------------------------------------------------------------------------
__global__ void __launch_bounds__(RED_THREADS, 4) wra_reduce(
    const float* __restrict__ pred,
    const float* __restrict__ truec,
    const float* __restrict__ wts,
    const uint32_t* __restrict__ mask)
{
    const int b = blockIdx.y;
    const int chunk = blockIdx.x;
    const float4* __restrict__ p4 = reinterpret_cast<const float4*>(pred  + (size_t)b * NPTS * 3);
    const float4* __restrict__ t4 = reinterpret_cast<const float4*>(truec + (size_t)b * NPTS * 3);
    const float4* __restrict__ w4 = reinterpret_cast<const float4*>(wts   + (size_t)b * NPTS);
    const uint4* __restrict__ m4  = reinterpret_cast<const uint4*>(mask + (size_t)b * NPTS);

    float acc[16];
#pragma unroll
    for (int i = 0; i < 16; i++) acc[i] = 0.f;

    const int g0 = chunk * GRP_PER_CHUNK;
#pragma unroll
    for (int it = 0; it < GRP_PER_CHUNK / RED_THREADS; it++) {
        const int g = g0 + it * RED_THREADS + threadIdx.x;
        float4 a0 = __ldg(&p4[3*g+0]), a1 = __ldg(&p4[3*g+1]), a2 = __ldg(&p4[3*g+2]);
        float4 c0 = __ldcs(&t4[3*g+0]), c1 = __ldcs(&t4[3*g+1]), c2 = __ldcs(&t4[3*g+2]);
        float4 wv = __ldcs(&w4[g]);
        uint4  mv = __ldg(&m4[g]);

        float px[4] = {a0.x, a0.w, a1.z, a2.y};
        float py[4] = {a0.y, a1.x, a1.w, a2.z};
        float pz[4] = {a0.z, a1.y, a2.x, a2.w};
        float tx[4] = {c0.x, c0.w, c1.z, c2.y};
        float ty[4] = {c0.y, c1.x, c1.w, c2.z};
        float tz[4] = {c0.z, c1.y, c2.x, c2.w};
        float ww[4] = {wv.x, wv.y, wv.z, wv.w};
        uint32_t mm[4] = {mv.x, mv.y, mv.z, mv.w};

#pragma unroll
        for (int k = 0; k < 4; k++) {
            float wi = (mm[k] != 0u) ? ww[k] : 0.f;
            float wtx = wi * tx[k], wty = wi * ty[k], wtz = wi * tz[k];
            acc[0]  += wi;
            acc[1]  += wi * px[k];
            acc[2]  += wi * py[k];
            acc[3]  += wi * pz[k];
            acc[4]  += wtx;
            acc[5]  += wty;
            acc[6]  += wtz;
            acc[7]  += wtx * px[k];
            acc[8]  += wtx * py[k];
            acc[9]  += wtx * pz[k];
            acc[10] += wty * px[k];
            acc[11] += wty * py[k];
            acc[12] += wty * pz[k];
            acc[13] += wtz * px[k];
            acc[14] += wtz * py[k];
            acc[15] += wtz * pz[k];
        }
    }

    // warp tree-reduce each accumulator
#pragma unroll
    for (int i = 0; i < 16; i++) {
#pragma unroll
        for (int o = 16; o > 0; o >>= 1)
            acc[i] += __shfl_down_sync(0xffffffffu, acc[i], o);
    }

    __shared__ float sh[RED_THREADS / 32][16];
    const int warp = threadIdx.x >> 5, lane = threadIdx.x & 31;
    if (lane == 0) {
#pragma unroll
        for (int i = 0; i < 16; i++) sh[warp][i] = acc[i];
    }
    __syncthreads();
    if (threadIdx.x < 16) {
        float s = 0.f;
#pragma unroll
        for (int w = 0; w < RED_THREADS / 32; w++) s += sh[w][threadIdx.x];
        g_part[b][chunk][threadIdx.x] = s;
    }
    __syncthreads();

    // last-arriving chunk block of this batch performs the solve
    if (threadIdx.x == 0) {
        __threadfence();                                  // publish g_part
        unsigned prev = atomicAdd(&g_cnt[b], 1u);
        if (prev == CHUNKS - 1) {
            __threadfence();                              // acquire peers' g_part
            float sums[16];
#pragma unroll
            for (int i = 0; i < 16; i++) {
                float s = 0.f;
#pragma unroll
                for (int c = 0; c < CHUNKS; c++) s += g_part[b][c][i];
                sums[i] = s;
            }
            float rt[15];
            kabsch_solve(sums, rt);
#pragma unroll
            for (int i = 0; i < 15; i++) g_rt[b][i] = rt[i];
            g_cnt[b] = 0u;                                // reset for next replay
        }
    }
}

// ---------------------------------------------------------------------------
// Kernel 2: apply  out = ((mask?pred:0) - pc) @ R + tc
// 4 groups per thread: 16 independent 16B loads in flight before compute.
// ---------------------------------------------------------------------------
#define APPLY_GPT 4
#define APPLY_THREADS 256
#define APPLY_BLKX ((NPTS / 4) / (APPLY_THREADS * APPLY_GPT))   // 4

__global__ void __launch_bounds__(APPLY_THREADS, 3) wra_apply(
    const float* __restrict__ pred,
    const uint32_t* __restrict__ mask,
    float* __restrict__ out)
{
    const int b = BATCH - 1 - blockIdx.y;   // reverse batch order (L2 recency)
    __shared__ float prm[15];
    if (threadIdx.x < 15) prm[threadIdx.x] = g_rt[b][threadIdx.x];
    __syncthreads();
    const float r00 = prm[0], r01 = prm[1], r02 = prm[2];
    const float r10 = prm[3], r11 = prm[4], r12 = prm[5];
    const float r20 = prm[6], r21 = prm[7], r22 = prm[8];
    const float pc0 = prm[9], pc1 = prm[10], pc2 = prm[11];
    const float tc0 = prm[12], tc1 = prm[13], tc2 = prm[14];

    const float4* __restrict__ p4 = reinterpret_cast<const float4*>(pred + (size_t)b * NPTS * 3);
    float4* __restrict__ o4 = reinterpret_cast<float4*>(out + (size_t)b * NPTS * 3);
    const uint4* __restrict__ m4 = reinterpret_cast<const uint4*>(mask + (size_t)b * NPTS);

    const int gbase = blockIdx.x * (APPLY_THREADS * APPLY_GPT) + threadIdx.x;

    // Front-batch all loads: 16 independent 16B transactions
    float4 A0[APPLY_GPT], A1[APPLY_GPT], A2[APPLY_GPT];
    uint4  MV[APPLY_GPT];
#pragma unroll
    for (int j = 0; j < APPLY_GPT; j++) {
        const int g = gbase + j * APPLY_THREADS;
        A0[j] = __ldg(&p4[3*g+0]);
        A1[j] = __ldg(&p4[3*g+1]);
        A2[j] = __ldg(&p4[3*g+2]);
        MV[j] = __ldg(&m4[g]);
    }

#pragma unroll
    for (int j = 0; j < APPLY_GPT; j++) {
        const int g = gbase + j * APPLY_THREADS;
        float px[4] = {A0[j].x, A0[j].w, A1[j].z, A2[j].y};
        float py[4] = {A0[j].y, A1[j].x, A1[j].w, A2[j].z};
        float pz[4] = {A0[j].z, A1[j].y, A2[j].x, A2[j].w};
        uint32_t mm[4] = {MV[j].x, MV[j].y, MV[j].z, MV[j].w};
        float ox[4], oy[4], oz[4];
#pragma unroll
        for (int k = 0; k < 4; k++) {
            bool mk = (mm[k] != 0u);
            float cx = (mk ? px[k] : 0.f) - pc0;
            float cy = (mk ? py[k] : 0.f) - pc1;
            float cz = (mk ? pz[k] : 0.f) - pc2;
            ox[k] = cx * r00 + cy * r10 + cz * r20 + tc0;
            oy[k] = cx * r01 + cy * r11 + cz * r21 + tc1;
            oz[k] = cx * r02 + cy * r12 + cz * r22 + tc2;
        }
        float4 o0 = {ox[0], oy[0], oz[0], ox[1]};
        float4 o1 = {oy[1], oz[1], ox[2], oy[2]};
        float4 o2 = {oz[2], ox[3], oy[3], oz[3]};
        __stcs(&o4[3*g+0], o0);
        __stcs(&o4[3*g+1], o1);
        __stcs(&o4[3*g+2], o2);
    }
}

// ---------------------------------------------------------------------------
extern "C" void kernel_launch(void* const* d_in, const int* in_sizes, int n_in,
                              void* d_out, int out_size) {
    const float*    pred  = (const float*)d_in[0];
    const float*    truec = (const float*)d_in[1];
    const float*    wts   = (const float*)d_in[2];
    const uint32_t* mask  = (const uint32_t*)d_in[3];
    float* out = (float*)d_out;

    wra_reduce<<<dim3(CHUNKS, BATCH), RED_THREADS>>>(pred, truec, wts, mask);
    wra_apply<<<dim3(APPLY_BLKX, BATCH), APPLY_THREADS>>>(pred, mask, out);
}